// round 2
// baseline (speedup 1.0000x reference)
#include <cuda_runtime.h>
#include <cuda_bf16.h>

#define BATCH   2048
#define TSTEPS  128
#define SLEN    256
#define HID     64
#define EMB     32
#define VOCAB   29
#define GATES   256          // 4*HID
#define XDIM    128          // [context(64), h(64)]
#define ENCPAD  68           // padded row stride in floats (conflict-free)

// Precomputed tables (device globals — allocation-free scratch)
__device__ float g_vocabW[VOCAB * GATES];   // emb@W_ih[:, :32]^T + b_ih + b_hh
__device__ float g_WT[XDIM * GATES];        // WT[k][j]: k<64 -> W_ih[j][32+k], else W_hh[j][k-64]
__device__ float g_fcT[XDIM * 32];          // fcT[d][v] = fc_W[v][d] (v<29 else 0)

struct __align__(16) Smem {
    float enc[2][SLEN * ENCPAD];   // 139264 B
    float vocabW[VOCAB * GATES];   //  29696 B
    float fcT[XDIM * 32];          //  16384 B
    float sc[2][SLEN];             //   2048 B (scores -> p -> activated gates)
    float cp[2][8][HID];           //   4096 B context partials per warp
    float part[2][2][GATES];       //   8192 B gate partials [b][half][j]
    float fp[2][8][32];            //   2048 B fc partials
    float h[2][HID];
    float c[2][HID];
    float ctx[2][HID];
    float wred[2][8];
    float wsum[2][8];
    float fcb[32];
    int   ybuf[2][TSTEPS];         //   1024 B
};

__global__ void setup_vocabW(const float* __restrict__ emb,
                             const float* __restrict__ W_ih,
                             const float* __restrict__ b_ih,
                             const float* __restrict__ b_hh) {
    int v = blockIdx.x, j = threadIdx.x;
    float acc = b_ih[j] + b_hh[j];
#pragma unroll
    for (int e = 0; e < EMB; e++)
        acc += emb[v * EMB + e] * W_ih[j * (EMB + HID) + e];
    g_vocabW[v * GATES + j] = acc;
}

__global__ void setup_WT(const float* __restrict__ W_ih,
                         const float* __restrict__ W_hh) {
    int k = blockIdx.x, j = threadIdx.x;
    g_WT[k * GATES + j] = (k < HID) ? W_ih[j * (EMB + HID) + EMB + k]
                                    : W_hh[j * HID + (k - HID)];
}

__global__ void setup_fcT(const float* __restrict__ fc_W) {
    int d = blockIdx.x, v = threadIdx.x;   // block 32
    g_fcT[d * 32 + v] = (v < VOCAB) ? fc_W[v * XDIM + d] : 0.0f;
}

__global__ __launch_bounds__(512, 1)
void decoder_kernel(const int* __restrict__ y,
                    const float* __restrict__ h0,
                    const float* __restrict__ c0,
                    const float* __restrict__ enc,
                    const float* __restrict__ fc_b,
                    float* __restrict__ out) {
    extern __shared__ char smem_raw[];
    Smem& S = *reinterpret_cast<Smem*>(smem_raw);

    const int tid  = threadIdx.x;
    const int g    = tid >> 8;        // batch group 0/1
    const int r    = tid & 255;       // rank within group
    const int lane = tid & 31;
    const int bglob = blockIdx.x * 2 + g;

    // Gate-weight slice in registers: thread (half=g, j=r) holds 64 floats
    float W[64];
#pragma unroll
    for (int k = 0; k < 64; k++)
        W[k] = g_WT[(g * 64 + k) * GATES + r];

    // ---- Prologue: fill shared memory ----
    for (int i = tid; i < XDIM * 32; i += 512) S.fcT[i] = g_fcT[i];
    for (int i = tid; i < VOCAB * GATES; i += 512) S.vocabW[i] = g_vocabW[i];
    if (tid < VOCAB) S.fcb[tid] = fc_b[tid];
    // enc tiles (padded rows), coalesced float4 loads
    for (int i = tid; i < 2 * 4096; i += 512) {
        int gg = i >> 12, idx4 = i & 4095;
        int s = idx4 >> 4, h4 = idx4 & 15;
        float4 v4 = reinterpret_cast<const float4*>(enc)[(size_t)(blockIdx.x * 2 + gg) * 4096 + idx4];
        *reinterpret_cast<float4*>(&S.enc[gg][s * ENCPAD + h4 * 4]) = v4;
    }
    if (r < HID) {
        S.h[g][r] = h0[bglob * HID + r];
        S.c[g][r] = c0[bglob * HID + r];
    }
    for (int i = tid; i < 2 * TSTEPS; i += 512) {
        int gg = i >> 7, tt = i & 127;
        S.ybuf[gg][tt] = y[(blockIdx.x * 2 + gg) * TSTEPS + tt];
    }
    __syncthreads();

    // ---- Timestep loop ----
    for (int t = 0; t < TSTEPS; t++) {
        // Phase A: scores[s] = enc[s,:] . h  (thread r == s)
        float score;
        {
            const float4* erow = reinterpret_cast<const float4*>(&S.enc[g][r * ENCPAD]);
            const float4* hv   = reinterpret_cast<const float4*>(S.h[g]);
            float acc = 0.f;
#pragma unroll
            for (int k = 0; k < 16; k++) {
                float4 e = erow[k], hh = hv[k];
                acc += e.x * hh.x + e.y * hh.y + e.z * hh.z + e.w * hh.w;
            }
            score = acc;
            float m = acc;
#pragma unroll
            for (int o = 16; o; o >>= 1) m = fmaxf(m, __shfl_xor_sync(~0u, m, o));
            if (lane == 0) S.wred[g][r >> 5] = m;
        }
        __syncthreads();
        // Phase B: global max, exp, warp sums (deferred normalization)
        {
            float M = S.wred[g][0];
#pragma unroll
            for (int i = 1; i < 8; i++) M = fmaxf(M, S.wred[g][i]);
            float p = __expf(score - M);
            S.sc[g][r] = p;
#pragma unroll
            for (int o = 16; o; o >>= 1) p += __shfl_xor_sync(~0u, p, o);
            if (lane == 0) S.wsum[g][r >> 5] = p;
        }
        __syncthreads();
        // Phase C: context partials. Warp w covers s in [32w,32w+32); lane = h/2 pair.
        {
            int w = r >> 5;
            float cx = 0.f, cy = 0.f;
            const int sbase = w * 32;
#pragma unroll 8
            for (int i = 0; i < 32; i++) {
                int s = sbase + i;
                float p = S.sc[g][s];
                float2 e = *reinterpret_cast<const float2*>(&S.enc[g][s * ENCPAD + 2 * lane]);
                cx += p * e.x;
                cy += p * e.y;
            }
            *reinterpret_cast<float2*>(&S.cp[g][w][2 * lane]) = make_float2(cx, cy);
        }
        __syncthreads();
        // Phase C2: reduce 8 warps + normalize
        if (r < HID) {
            float ssum = 0.f;
#pragma unroll
            for (int i = 0; i < 8; i++) ssum += S.wsum[g][i];
            float a = 0.f;
#pragma unroll
            for (int w = 0; w < 8; w++) a += S.cp[g][w][r];
            S.ctx[g][r] = a / ssum;
        }
        __syncthreads();
        // Phase D: gate partials. thread (half=g, j=r) does both batches with reg weights.
        {
            const float* x0 = (g == 0) ? S.ctx[0] : S.h[0];
            const float* x1 = (g == 0) ? S.ctx[1] : S.h[1];
            float a0 = 0.f, a1 = 0.f;
#pragma unroll
            for (int k4 = 0; k4 < 16; k4++) {
                float4 v0 = reinterpret_cast<const float4*>(x0)[k4];
                float4 v1 = reinterpret_cast<const float4*>(x1)[k4];
                a0 += W[4*k4+0]*v0.x + W[4*k4+1]*v0.y + W[4*k4+2]*v0.z + W[4*k4+3]*v0.w;
                a1 += W[4*k4+0]*v1.x + W[4*k4+1]*v1.y + W[4*k4+2]*v1.z + W[4*k4+3]*v1.w;
            }
            S.part[0][g][r] = a0;
            S.part[1][g][r] = a1;
        }
        __syncthreads();
        // Phase E: combine + activations (thread handles gate r of batch g). Reuse S.sc.
        {
            int v = S.ybuf[g][t];
            float gate = S.vocabW[v * GATES + r] + S.part[g][0][r] + S.part[g][1][r];
            float act;
            if (r < 128 || r >= 192) act = 1.0f / (1.0f + __expf(-gate));  // i, f, o
            else                     act = tanhf(gate);                     // g
            S.sc[g][r] = act;
        }
        __syncthreads();
        // Phase F: LSTM state update
        if (r < HID) {
            float i_ = S.sc[g][r];
            float f_ = S.sc[g][64 + r];
            float g_ = S.sc[g][128 + r];
            float o_ = S.sc[g][192 + r];
            float cn = f_ * S.c[g][r] + i_ * g_;
            float hn = o_ * tanhf(cn);
            S.c[g][r] = cn;
            S.h[g][r] = hn;
        }
        __syncthreads();
        // Phase G: logits = [h_new, ctx] @ fc_W^T + fc_b  (8-way split dot)
        {
            int v = r & 31, p8 = r >> 5;
            float acc = 0.f;
#pragma unroll
            for (int i = 0; i < 16; i++) {
                int d = p8 * 16 + i;
                float cd = (d < HID) ? S.h[g][d] : S.ctx[g][d - HID];
                acc += cd * S.fcT[d * 32 + v];
            }
            S.fp[g][p8][v] = acc;
        }
        __syncthreads();
        if (r < VOCAB) {
            float acc = S.fcb[r];
#pragma unroll
            for (int p = 0; p < 8; p++) acc += S.fp[g][p][r];
            out[((size_t)bglob * TSTEPS + t) * VOCAB + r] = acc;
        }
        __syncthreads();
    }
}

extern "C" void kernel_launch(void* const* d_in, const int* in_sizes, int n_in,
                              void* d_out, int out_size) {
    const int*   y     = (const int*)  d_in[0];
    const float* h0    = (const float*)d_in[1];
    const float* c0    = (const float*)d_in[2];
    const float* enc   = (const float*)d_in[3];
    const float* emb   = (const float*)d_in[4];
    const float* W_ih  = (const float*)d_in[5];
    const float* W_hh  = (const float*)d_in[6];
    const float* b_ih  = (const float*)d_in[7];
    const float* b_hh  = (const float*)d_in[8];
    const float* fc_W  = (const float*)d_in[9];
    const float* fc_b  = (const float*)d_in[10];
    float* out = (float*)d_out;
    (void)in_sizes; (void)n_in; (void)out_size;

    setup_vocabW<<<VOCAB, GATES>>>(emb, W_ih, b_ih, b_hh);
    setup_WT<<<XDIM, GATES>>>(W_ih, W_hh);
    setup_fcT<<<XDIM, 32>>>(fc_W);

    cudaFuncSetAttribute(decoder_kernel,
                         cudaFuncAttributeMaxDynamicSharedMemorySize,
                         (int)sizeof(Smem));
    decoder_kernel<<<BATCH / 2, 512, sizeof(Smem)>>>(y, h0, c0, enc, fc_b, out);
}

// round 3
// speedup vs baseline: 1.9911x; 1.9911x over previous
#include <cuda_runtime.h>
#include <cuda_fp16.h>

#define BATCH   2048
#define TSTEPS  128
#define SLEN    256
#define HID     64
#define EMB     32
#define VOCAB   29
#define GATES   256          // 4*HID
#define ENCPAD  68           // padded enc row stride in floats (conflict-free)

// Precomputed tables (device globals — allocation-free scratch)
__device__ float   g_vocabW[VOCAB * GATES];   // emb@W_ih[:, :32]^T + b_ih + b_hh  (fp32)
__device__ __half2 g_WTh[64 * GATES];         // W pairs: g_WTh[k2*256+j] = (WT[2k2][j], WT[2k2+1][j]) fp16
__device__ float   g_fcT[128 * 32];           // fcT[d][v] = fc_W[v][d] (v<29 else 0)

struct __align__(16) Smem {
    float enc[SLEN * ENCPAD];   // 69632 B
    float p[SLEN];              //  1024 B  (unnormalized softmax weights)
    float cp[8][2][HID];        //  4096 B  context partials [warp][sub][h]
    float ctx[HID];             //   256 B
    float h[HID];               //   256 B
    float act[GATES];           //  1024 B  activated gates
    float fp[8][32];            //  1024 B  fc partials
    float wsum[8];              //    32 B
    int   ybuf[TSTEPS];         //   512 B
};  // ~77.8 KB

__global__ void setup_vocabW(const float* __restrict__ emb,
                             const float* __restrict__ W_ih,
                             const float* __restrict__ b_ih,
                             const float* __restrict__ b_hh) {
    int v = blockIdx.x, j = threadIdx.x;
    float acc = b_ih[j] + b_hh[j];
#pragma unroll
    for (int e = 0; e < EMB; e++)
        acc += emb[v * EMB + e] * W_ih[j * (EMB + HID) + e];
    g_vocabW[v * GATES + j] = acc;
}

__device__ __forceinline__ float wt_elem(const float* W_ih, const float* W_hh, int k, int j) {
    // x = [ctx(64), h(64)]
    return (k < HID) ? W_ih[j * (EMB + HID) + EMB + k] : W_hh[j * HID + (k - HID)];
}

__global__ void setup_WTh(const float* __restrict__ W_ih,
                          const float* __restrict__ W_hh) {
    int k2 = blockIdx.x, j = threadIdx.x;   // k2 in [0,64)
    float w0 = wt_elem(W_ih, W_hh, 2 * k2 + 0, j);
    float w1 = wt_elem(W_ih, W_hh, 2 * k2 + 1, j);
    g_WTh[k2 * GATES + j] = __floats2half2_rn(w0, w1);
}

__global__ void setup_fcT(const float* __restrict__ fc_W) {
    int d = blockIdx.x, v = threadIdx.x;   // grid 128, block 32
    g_fcT[d * 32 + v] = (v < VOCAB) ? fc_W[v * 2 * HID + d] : 0.0f;
}

__global__ __launch_bounds__(256, 2)
void decoder_kernel(const int* __restrict__ y,
                    const float* __restrict__ h0,
                    const float* __restrict__ c0,
                    const float* __restrict__ enc,
                    const float* __restrict__ fc_b,
                    float* __restrict__ out) {
    extern __shared__ char smem_raw[];
    Smem& S = *reinterpret_cast<Smem*>(smem_raw);

    const int tid  = threadIdx.x;
    const int lane = tid & 31;
    const int wid  = tid >> 5;
    const int b    = blockIdx.x;

    // ---- Gate weights in registers: thread j holds full 128-weight column as 64 half2 ----
    __half2 W2[64];
#pragma unroll
    for (int i = 0; i < 64; i++)
        W2[i] = g_WTh[i * GATES + tid];

    // ---- Prologue: fill shared memory ----
    {
        const float4* esrc = reinterpret_cast<const float4*>(enc) + (size_t)b * (SLEN * HID / 4);
#pragma unroll
        for (int it = 0; it < 16; it++) {
            int idx = tid + it * 256;              // 4096 float4s
            int s = idx >> 4, q = idx & 15;
            *reinterpret_cast<float4*>(&S.enc[s * ENCPAD + q * 4]) = esrc[idx];
        }
    }
    float c_reg = 0.f;
    if (tid < HID) {
        S.h[tid] = h0[b * HID + tid];
        c_reg    = c0[b * HID + tid];
    }
    if (tid < TSTEPS) S.ybuf[tid] = y[b * TSTEPS + tid];
    __syncthreads();

    const float4* hF4   = reinterpret_cast<const float4*>(S.h);
    const float4* ctxF4 = reinterpret_cast<const float4*>(S.ctx);
    const float4* erow  = reinterpret_cast<const float4*>(&S.enc[tid * ENCPAD]);

    // ---- Timestep loop ----
    for (int t = 0; t < TSTEPS; t++) {
        // Phase A: score[s=tid] = enc[s,:].h ; p = exp(score) (no max: scores bounded << 88)
        {
            float a0 = 0.f, a1 = 0.f;
#pragma unroll
            for (int k = 0; k < 16; k += 2) {
                float4 e0 = erow[k],     hh0 = hF4[k];
                float4 e1 = erow[k + 1], hh1 = hF4[k + 1];
                a0 += e0.x*hh0.x + e0.y*hh0.y + e0.z*hh0.z + e0.w*hh0.w;
                a1 += e1.x*hh1.x + e1.y*hh1.y + e1.z*hh1.z + e1.w*hh1.w;
            }
            float p = __expf(a0 + a1);
            S.p[tid] = p;
#pragma unroll
            for (int o = 16; o; o >>= 1) p += __shfl_xor_sync(~0u, p, o);
            if (lane == 0) S.wsum[wid] = p;
        }
        __syncthreads();   // (1)

        // Phase B: context partials. Warp w covers s in [32w,32w+32).
        // lanes 0-15 -> even s, lanes 16-31 -> odd s; lane handles 4 h values (float4).
        {
            const int hi = lane >> 4, lo = lane & 15;
            const float* base = &S.enc[(wid * 32 + hi) * ENCPAD + lo * 4];
            float4 acc = make_float4(0.f, 0.f, 0.f, 0.f);
#pragma unroll
            for (int i = 0; i < 16; i++) {
                float2 pp = *reinterpret_cast<const float2*>(&S.p[wid * 32 + 2 * i]);
                float  p  = hi ? pp.y : pp.x;
                float4 e  = *reinterpret_cast<const float4*>(base + i * 2 * ENCPAD);
                acc.x += p * e.x; acc.y += p * e.y; acc.z += p * e.z; acc.w += p * e.w;
            }
            *reinterpret_cast<float4*>(&S.cp[wid][hi][lo * 4]) = acc;
        }
        __syncthreads();   // (2)

        // Phase C: reduce partials + normalize -> ctx
        if (tid < HID) {
            float z = S.wsum[0];
#pragma unroll
            for (int i = 1; i < 8; i++) z += S.wsum[i];
            float a = 0.f;
#pragma unroll
            for (int w = 0; w < 8; w++) a += S.cp[w][0][tid] + S.cp[w][1][tid];
            S.ctx[tid] = a * (1.0f / z);
        }
        __syncthreads();   // (3)

        // Phase D: gate j=tid, full 128-dot with register weights (fp16 pairs)
        {
            float acc0 = 0.f, acc1 = 0.f;
#pragma unroll
            for (int i = 0; i < 16; i++) {
                float4 x = ctxF4[i];
                float2 wa = __half22float2(W2[2 * i]);
                float2 wb = __half22float2(W2[2 * i + 1]);
                acc0 += wa.x * x.x + wa.y * x.y;
                acc1 += wb.x * x.z + wb.y * x.w;
            }
#pragma unroll
            for (int i = 0; i < 16; i++) {
                float4 x = hF4[i];
                float2 wa = __half22float2(W2[32 + 2 * i]);
                float2 wb = __half22float2(W2[33 + 2 * i]);
                acc0 += wa.x * x.x + wa.y * x.y;
                acc1 += wb.x * x.z + wb.y * x.w;
            }
            int v = S.ybuf[t];
            float gate = acc0 + acc1 + __ldg(&g_vocabW[v * GATES + tid]);
            float a;
            if (tid < 128 || tid >= 192) a = 1.0f / (1.0f + __expf(-gate));  // i, f, o
            else                         a = tanhf(gate);                     // g
            S.act[tid] = a;
        }
        __syncthreads();   // (4)

        // Phase E: LSTM state update (c in registers of threads 0..63)
        if (tid < HID) {
            float i_ = S.act[tid];
            float f_ = S.act[HID + tid];
            float g_ = S.act[2 * HID + tid];
            float o_ = S.act[3 * HID + tid];
            c_reg = f_ * c_reg + i_ * g_;
            S.h[tid] = o_ * tanhf(c_reg);
        }
        __syncthreads();   // (5)

        // Phase F: logits partials. warp w covers d in [16w,16w+16); lane = vocab slot.
        {
            const float* src = (wid < 4) ? (S.h + wid * 16) : (S.ctx + (wid - 4) * 16);
            const int dbase = wid * 16;
            float acc = 0.f;
#pragma unroll
            for (int i = 0; i < 16; i++)
                acc += src[i] * __ldg(&g_fcT[(dbase + i) * 32 + lane]);
            S.fp[wid][lane] = acc;
        }
        __syncthreads();   // (6)

        if (tid < VOCAB) {
            float acc = __ldg(&fc_b[tid]);
#pragma unroll
            for (int w = 0; w < 8; w++) acc += S.fp[w][tid];
            out[((size_t)b * TSTEPS + t) * VOCAB + tid] = acc;
        }
        // No barrier needed here: next writers of S.fp / S.p are >=1 barrier away
        // and in-thread ordering protects the output readers.
    }
}

extern "C" void kernel_launch(void* const* d_in, const int* in_sizes, int n_in,
                              void* d_out, int out_size) {
    const int*   y     = (const int*)  d_in[0];
    const float* h0    = (const float*)d_in[1];
    const float* c0    = (const float*)d_in[2];
    const float* enc   = (const float*)d_in[3];
    const float* emb   = (const float*)d_in[4];
    const float* W_ih  = (const float*)d_in[5];
    const float* W_hh  = (const float*)d_in[6];
    const float* b_ih  = (const float*)d_in[7];
    const float* b_hh  = (const float*)d_in[8];
    const float* fc_W  = (const float*)d_in[9];
    const float* fc_b  = (const float*)d_in[10];
    float* out = (float*)d_out;
    (void)in_sizes; (void)n_in; (void)out_size;

    setup_vocabW<<<VOCAB, GATES>>>(emb, W_ih, b_ih, b_hh);
    setup_WTh<<<64, GATES>>>(W_ih, W_hh);
    setup_fcT<<<128, 32>>>(fc_W);

    cudaFuncSetAttribute(decoder_kernel,
                         cudaFuncAttributeMaxDynamicSharedMemorySize,
                         (int)sizeof(Smem));
    decoder_kernel<<<BATCH, 256, sizeof(Smem)>>>(y, h0, c0, enc, fc_b, out);
}